// round 8
// baseline (speedup 1.0000x reference)
#include <cuda_runtime.h>

#define IMG_W 512
#define IMG_H 512
#define N_IMG 48            // 16 batch * 3 channels
#define HT 8                // output rows per block strip
#define N_STRIPS (IMG_H / HT)
#define NBLK (N_STRIPS * N_IMG)
#define SW 528              // smem columns: s=x+8, pad keeps float4 alignment
#define NT 256              // 8 warps
#define SM_FLOATS (4 * HT * SW)
#define SMEM_BYTES ((SM_FLOATS + 8) * 4)

// zero-initialized at module load; last block of each launch resets them,
// so every graph replay starts from zero (deterministic).
__device__ double g_acc;
__device__ unsigned int g_cnt;

#define WG_INIT {0.00102838f, 0.00759876f, 0.03600077f, 0.10936069f, \
                 0.21300554f, 0.26601173f, 0.21300554f, 0.10936069f, \
                 0.03600077f, 0.00759876f, 0.00102838f}

// 11-tap conv producing 8 outputs (x = 8o .. 8o+7) from one smem row.
// Reads 6 aligned float4 (s = 8o .. 8o+23); taps need s in [8o+3, 8o+20].
__device__ __forceinline__ void conv8(const float* __restrict__ row, int o,
                                      float* __restrict__ out) {
    const float wg[11] = WG_INIT;
    float v[24];
    const float4* rp = (const float4*)row + 2 * o;
    #pragma unroll
    for (int b = 0; b < 6; b++) {
        float4 f = rp[b];
        v[4 * b + 0] = f.x; v[4 * b + 1] = f.y;
        v[4 * b + 2] = f.z; v[4 * b + 3] = f.w;
    }
    #pragma unroll
    for (int j = 0; j < 8; j++) {
        float a = 0.f;
        #pragma unroll
        for (int k = 0; k < 11; k++) a = fmaf(wg[k], v[3 + j + k], a);
        out[j] = a;
    }
}

__global__ void __launch_bounds__(NT, 2) ssim_fused(const float* __restrict__ pred,
                                                    const float* __restrict__ tgt,
                                                    float* __restrict__ out) {
    extern __shared__ float sm[];
    float* wsum = sm + SM_FLOATS;
    const float wg[11] = WG_INIT;

    const int img  = blockIdx.y;
    const int row0 = blockIdx.x * HT;
    const float* P = pred + (size_t)img * (IMG_W * IMG_H);
    const float* T = tgt  + (size_t)img * (IMG_W * IMG_H);
    const bool interior = (row0 >= 5) && (row0 + HT + 5 <= IMG_H);

    // ---------------- Vertical pass: global -> smem (4 channels) ----------------
    for (int s = threadIdx.x; s < SW; s += NT) {
        const int x = s - 8;
        if (x < 0 || x >= IMG_W) {
            #pragma unroll
            for (int r = 0; r < HT; r++) {
                sm[(0 * HT + r) * SW + s] = 0.f;
                sm[(1 * HT + r) * SW + s] = 0.f;
                sm[(2 * HT + r) * SW + s] = 0.f;
                sm[(3 * HT + r) * SW + s] = 0.f;
            }
            continue;
        }
        float pv[HT + 10], tv[HT + 10], sv[HT + 10], qv[HT + 10];
        if (interior) {
            const float* pc = P + (row0 - 5) * IMG_W + x;
            const float* tc = T + (row0 - 5) * IMG_W + x;
            #pragma unroll
            for (int i = 0; i < HT + 10; i++) {
                float p = pc[i * IMG_W], t = tc[i * IMG_W];
                pv[i] = p; tv[i] = t;
                sv[i] = fmaf(t, t, p * p);   // p^2 + t^2 combined channel
                qv[i] = p * t;               // hoisted product (computed once)
            }
        } else {
            #pragma unroll
            for (int i = 0; i < HT + 10; i++) {
                const int row = row0 - 5 + i;
                const bool ok = (row >= 0) && (row < IMG_H);
                float p = ok ? P[row * IMG_W + x] : 0.f;
                float t = ok ? T[row * IMG_W + x] : 0.f;
                pv[i] = p; tv[i] = t;
                sv[i] = fmaf(t, t, p * p);
                qv[i] = p * t;
            }
        }
        #pragma unroll
        for (int r = 0; r < HT; r++) {
            float mp = 0.f, mt = 0.f, ms = 0.f, mq = 0.f;
            #pragma unroll
            for (int k = 0; k < 11; k++) {
                mp = fmaf(wg[k], pv[r + k], mp);
                mt = fmaf(wg[k], tv[r + k], mt);
                ms = fmaf(wg[k], sv[r + k], ms);
                mq = fmaf(wg[k], qv[r + k], mq);
            }
            sm[(0 * HT + r) * SW + s] = mp;
            sm[(1 * HT + r) * SW + s] = mt;
            sm[(2 * HT + r) * SW + s] = ms;
            sm[(3 * HT + r) * SW + s] = mq;
        }
    }
    __syncthreads();

    // ---------------- Horizontal pass + SSIM formula + reduce ----------------
    const float C1 = 1e-4f, C2 = 9e-4f;
    float acc = 0.f;
    #pragma unroll 1
    for (int task = threadIdx.x; task < HT * (IMG_W / 8); task += NT) {
        const int r = task >> 6;     // row within strip
        const int o = task & 63;     // oct index: outputs x = 8o .. 8o+7
        float h0[8], h1[8], h2[8], h3[8];
        conv8(sm + (0 * HT + r) * SW, o, h0);
        conv8(sm + (1 * HT + r) * SW, o, h1);
        conv8(sm + (2 * HT + r) * SW, o, h2);
        conv8(sm + (3 * HT + r) * SW, o, h3);
        #pragma unroll
        for (int j = 0; j < 8; j++) {
            float mx  = h0[j], my = h1[j];
            float mx2 = mx * mx, my2 = my * my, mxy = mx * my;
            float sgs  = h2[j] - mx2 - my2;   // sg_x + sg_y
            float sgxy = h3[j] - mxy;
            float num = (2.f * mxy + C1) * (2.f * sgxy + C2);
            float den = (mx2 + my2 + C1) * (sgs + C2);
            acc += __fdividef(num, den);
        }
    }

    // block reduction
    #pragma unroll
    for (int off = 16; off; off >>= 1)
        acc += __shfl_down_sync(0xffffffffu, acc, off);
    if ((threadIdx.x & 31) == 0) wsum[threadIdx.x >> 5] = acc;
    __syncthreads();

    if (threadIdx.x == 0) {
        float s = 0.f;
        #pragma unroll
        for (int i = 0; i < NT / 32; i++) s += wsum[i];
        atomicAdd(&g_acc, (double)s);
        __threadfence();
        unsigned int t = atomicAdd(&g_cnt, 1u);
        if (t == NBLK - 1) {
            // all blocks' g_acc adds are visible (fence before counter inc)
            double tot = atomicAdd(&g_acc, 0.0);   // coherent read (returns old)
            out[0] = 1.0f - (float)(tot / ((double)N_IMG * IMG_W * IMG_H));
            // reset for next graph replay
            g_acc = 0.0;
            g_cnt = 0u;
        }
    }
}

extern "C" void kernel_launch(void* const* d_in, const int* in_sizes, int n_in,
                              void* d_out, int out_size) {
    const float* pred = (const float*)d_in[0];
    const float* tgt  = (const float*)d_in[1];

    // 66 KB dynamic smem > 48 KB default: opt-in (host attribute, capture-safe)
    cudaFuncSetAttribute(ssim_fused, cudaFuncAttributeMaxDynamicSharedMemorySize,
                         SMEM_BYTES);

    dim3 grid(N_STRIPS, N_IMG);
    ssim_fused<<<grid, NT, SMEM_BYTES>>>(pred, tgt, (float*)d_out);
}